// round 15
// baseline (speedup 1.0000x reference)
#include <cuda_runtime.h>
#include <cuda_fp16.h>
#include <math.h>
#include <stdint.h>

#define T 2048
#define H 1024
#define F 2816
#define E 8
#define BK 64          // k (f16 elems) per pipeline stage
#define RSTRIDE 144    // padded row stride in bytes (72 halves)
#define NSTAGE 3

// ---------------- scratch (__device__ globals: allocation-free rule) --------
__device__ int    g_cnt[E];                     // zero-init; re-zeroed by combine
__device__ int    g_tok[E * T];
__device__ float  g_wt [E * T];
__device__ int    g_inv[2 * T];                 // token -> slot (e*T+p)
__device__ __half g_xh [(size_t)T * H];         // fp16 x
__device__ __half g_hh [(size_t)E * T * F];     // fp16 hidden
__device__ __half g_w1h[(size_t)E * F * H];
__device__ __half g_w3h[(size_t)E * F * H];
__device__ __half g_w2h[(size_t)E * H * F];
__device__ float  g_y  [(size_t)E * T * H];     // unweighted expert outputs

// ---------------- helpers ---------------------------------------------------
__device__ __forceinline__ unsigned h2u(__half2 h) {
    union { __half2 h; unsigned u; } c; c.h = h; return c.u;
}
__device__ __forceinline__ unsigned long long pack2(unsigned lo, unsigned hi) {
    return (unsigned long long)lo | ((unsigned long long)hi << 32);
}
__device__ __forceinline__ void mma_f16(float d[4], const unsigned a[4],
                                        const unsigned b0, const unsigned b1) {
    asm volatile(
        "mma.sync.aligned.m16n8k16.row.col.f32.f16.f16.f32 "
        "{%0,%1,%2,%3}, {%4,%5,%6,%7}, {%8,%9}, {%0,%1,%2,%3};\n"
        : "+f"(d[0]), "+f"(d[1]), "+f"(d[2]), "+f"(d[3])
        : "r"(a[0]), "r"(a[1]), "r"(a[2]), "r"(a[3]),
          "r"(b0), "r"(b1));
}
__device__ __forceinline__ void ldsm4(unsigned r[4], uint32_t addr) {
    asm volatile("ldmatrix.sync.aligned.m8n8.x4.shared.b16 {%0,%1,%2,%3}, [%4];"
                 : "=r"(r[0]), "=r"(r[1]), "=r"(r[2]), "=r"(r[3]) : "r"(addr));
}
__device__ __forceinline__ void cpa16(uint32_t dst, const void* src) {
    asm volatile("cp.async.cg.shared.global [%0], [%1], 16;" :: "r"(dst), "l"(src));
}
#define CP_COMMIT() asm volatile("cp.async.commit_group;")
#define CP_WAIT1()  asm volatile("cp.async.wait_group 1;")
__device__ __forceinline__ uint32_t smem_u32(const void* p) {
    return (uint32_t)__cvta_generic_to_shared(p);
}

#define TILE0   1024
#define A_BYTES (128 * RSTRIDE)                  // 18432
#define STAGE_B (2 * A_BYTES)                    // 36864 (A + B)
#define SMEM_SZ (TILE0 + NSTAGE * STAGE_B)       // 111616 -> 2 CTAs/SM

// ---------------- kernel: prep13 (w1, w3 of experts [e0,e1) -> fp16) --------
__global__ void k_prep13(const float* __restrict__ w1,
                         const float* __restrict__ w3, int e0, int e1) {
    const size_t base = (size_t)e0 * F * H / 4;
    const size_t n4 = (size_t)(e1 - e0) * F * H / 4;
    size_t stride = (size_t)gridDim.x * blockDim.x;
    for (size_t k = blockIdx.x * (size_t)blockDim.x + threadIdx.x; k < n4; k += stride) {
        size_t i = base + k;
        float4 a = __ldcs((const float4*)w1 + i);
        __stcs((unsigned long long*)((uint2*)g_w1h + i),
               pack2(h2u(__floats2half2_rn(a.x, a.y)),
                     h2u(__floats2half2_rn(a.z, a.w))));
        float4 b = __ldcs((const float4*)w3 + i);
        __stcs((unsigned long long*)((uint2*)g_w3h + i),
               pack2(h2u(__floats2half2_rn(b.x, b.y)),
                     h2u(__floats2half2_rn(b.z, b.w))));
    }
}

// ---------------- kernel: prep2 (w2 -> fp16; streaming) ---------------------
__global__ void k_prep2(const float* __restrict__ w2) {
    const size_t n4 = (size_t)E * F * H / 4;
    size_t stride = (size_t)gridDim.x * blockDim.x;
    for (size_t i = blockIdx.x * (size_t)blockDim.x + threadIdx.x; i < n4; i += stride) {
        float4 c = __ldcs((const float4*)w2 + i);
        __stcs((unsigned long long*)((uint2*)g_w2h + i),
               pack2(h2u(__floats2half2_rn(c.x, c.y)),
                     h2u(__floats2half2_rn(c.z, c.w))));
    }
}

// ---------------- kernel: init (x -> fp16) ----------------------------------
__global__ void k_init(const float* __restrict__ x) {
    const int n4 = T * H / 4;
    for (int i = blockIdx.x * blockDim.x + threadIdx.x; i < n4;
         i += gridDim.x * blockDim.x) {
        float4 a = ((const float4*)x)[i];
        uint2 p; p.x = h2u(__floats2half2_rn(a.x, a.y));
        p.y = h2u(__floats2half2_rn(a.z, a.w));
        ((uint2*)g_xh)[i] = p;
    }
}

// ---------------- kernel: router (vectorized; cnt pre-zeroed by combine) ----
__global__ void k_router(const float* __restrict__ x, const float* __restrict__ gw) {
    int warp = (blockIdx.x * blockDim.x + threadIdx.x) >> 5;
    int lane = threadIdx.x & 31;
    if (warp >= T) return;
    const float4* xr = (const float4*)(x + (size_t)warp * H);
    float4 xv[8];
#pragma unroll
    for (int q = 0; q < 8; q++) xv[q] = xr[lane + q * 32];
    float logit[E];
#pragma unroll
    for (int e = 0; e < E; e++) {
        const float4* g4 = (const float4*)(gw + (size_t)e * H);
        float p = 0.0f;
#pragma unroll
        for (int q = 0; q < 8; q++) {
            float4 gv = g4[lane + q * 32];
            p += xv[q].x * gv.x + xv[q].y * gv.y + xv[q].z * gv.z + xv[q].w * gv.w;
        }
#pragma unroll
        for (int o = 16; o; o >>= 1) p += __shfl_xor_sync(0xffffffffu, p, o);
        logit[e] = p;
    }
    if (lane == 0) {
        int i0 = 0; float v0 = logit[0];
#pragma unroll
        for (int e = 1; e < E; e++)
            if (logit[e] > v0) { v0 = logit[e]; i0 = e; }
        int i1 = -1; float v1 = -3.0e38f;
#pragma unroll
        for (int e = 0; e < E; e++)
            if (e != i0 && logit[e] > v1) { v1 = logit[e]; i1 = e; }
        float w0 = 1.0f / (1.0f + expf(v1 - v0));
        float w1 = 1.0f - w0;
        int p0 = atomicAdd(&g_cnt[i0], 1);
        g_tok[i0 * T + p0] = warp; g_wt[i0 * T + p0] = w0;
        g_inv[2 * warp + 0] = i0 * T + p0;
        int p1 = atomicAdd(&g_cnt[i1], 1);
        g_tok[i1 * T + p1] = warp; g_wt[i1 * T + p1] = w1;
        g_inv[2 * warp + 1] = i1 * T + p1;
    }
}

// ---------------- kernel: GEMM1 (fused w1/w3 interleaved) -> g_hh -----------
// grid (F/64, T/128, 4) for experts [ebase, ebase+4), block 128 threads
// (4 warps of 64x64), 2 CTA/SM (reg cap 256 -> no spill). 3-stage ring, wait1.
__global__ __launch_bounds__(128, 2)
void k_gemm1(int ebase) {
    int e = blockIdx.z + ebase;
    int cnt = g_cnt[e];
    int m0 = blockIdx.y * 128;
    if (m0 >= cnt) return;
    int n0f = blockIdx.x * 64;                   // FFN column base

    extern __shared__ char sm[];
    int* toks = (int*)sm;
    uint32_t sb = smem_u32(sm);

    int tid = threadIdx.x, wid = tid >> 5, lane = tid & 31;
    int wm = (wid & 1) * 64, wn = (wid >> 1) * 64;
    int lr = lane >> 2, lc = lane & 3;
    int lq = lane >> 3, lrr = lane & 7;

    toks[tid] = g_tok[e * T + min(m0 + tid, cnt - 1)];
    __syncthreads();

    const __half* w1e = g_w1h + ((size_t)e * F + n0f) * H;
    const __half* w3e = g_w3h + ((size_t)e * F + n0f) * H;

    float acc[4][8][4] = {};

    auto load_tile = [&](int s, int itile) {
        uint32_t abase = sb + TILE0 + s * STAGE_B;
        uint32_t bbase = abase + A_BYTES;
        int k0 = itile * BK;
#pragma unroll
        for (int q = 0; q < 8; q++) {            // A: 128 rows x 8 chunks
            int ch = tid + q * 128;
            int r = ch >> 3, c = ch & 7;
            cpa16(abase + r * RSTRIDE + c * 16,
                  g_xh + (size_t)toks[r] * H + k0 + c * 8);
        }
#pragma unroll
        for (int q = 0; q < 8; q++) {            // B: 128 interleaved rows x 8
            int ch = tid + q * 128;
            int r = ch >> 3, c = ch & 7;
            const __half* src = (r & 1) ? (w3e + (size_t)(r >> 1) * H + k0 + c * 8)
                                        : (w1e + (size_t)(r >> 1) * H + k0 + c * 8);
            cpa16(bbase + r * RSTRIDE + c * 16, src);
        }
    };

    load_tile(0, 0); CP_COMMIT();
    load_tile(1, 1); CP_COMMIT();

    const int NIT = H / BK;   // 16
    for (int it = 0; it < NIT; ++it) {
        CP_WAIT1();                      // tile it resident; it+1 may be in flight
        __syncthreads();                 // stage (it-1)%3 consumed by all warps
        if (it + 2 < NIT) load_tile((it + 2) % NSTAGE, it + 2);
        CP_COMMIT();

        uint32_t abase = sb + TILE0 + (it % NSTAGE) * STAGE_B;
        uint32_t bbase = abase + A_BYTES;
#pragma unroll
        for (int kk = 0; kk < BK; kk += 16) {
            unsigned a[4][4];
#pragma unroll
            for (int i = 0; i < 4; i++) {
                uint32_t ad = abase + (wm + i * 16 + (lane & 15)) * RSTRIDE
                            + kk * 2 + ((lane >> 4) << 4);
                ldsm4(a[i], ad);
            }
            uint32_t koff = (uint32_t)((kk + (lq & 1) * 8) * 2);
            unsigned bcur[4], bnxt[4];
            ldsm4(bcur, bbase + (wn + (lq >> 1) * 8 + lrr) * RSTRIDE + koff);
#pragma unroll
            for (int jp = 0; jp < 4; jp++) {
                if (jp < 3)
                    ldsm4(bnxt, bbase + (wn + (jp + 1) * 16 + (lq >> 1) * 8 + lrr)
                                 * RSTRIDE + koff);
#pragma unroll
                for (int jj = 0; jj < 2; jj++) {
                    int j = jp * 2 + jj;
#pragma unroll
                    for (int i = 0; i < 4; i++)
                        mma_f16(acc[i][j], a[i], bcur[jj * 2], bcur[jj * 2 + 1]);
                }
#pragma unroll
                for (int q = 0; q < 4; q++) bcur[q] = bnxt[q];
            }
        }
    }

    // epilogue: h = silu(g)*u (register-local), stage fp16 via smem
    __syncthreads();
    __half* hst = (__half*)(sm + TILE0);         // [128][72] halves
#pragma unroll
    for (int i = 0; i < 4; i++) {
#pragma unroll
        for (int p = 0; p < 2; p++) {
            int row = wm + i * 16 + p * 8 + lr;
#pragma unroll
            for (int j = 0; j < 8; j++) {
                float g = acc[i][j][p * 2 + 0];
                float u = acc[i][j][p * 2 + 1];
                float h = g / (1.0f + __expf(-g)) * u;
                int nf = (wn >> 1) + j * 4 + lc;
                hst[row * 72 + nf] = __float2half_rn(h);
            }
        }
    }
    __syncthreads();
#pragma unroll
    for (int q = 0; q < 8; q++) {                // 128 rows x 8 chunks of 8 halves
        int ch = tid + q * 128;
        int r = ch >> 3, c = ch & 7;
        float4 v = *(const float4*)(hst + r * 72 + c * 8);
        *(float4*)&g_hh[(size_t)(e * T + m0 + r) * F + n0f + c * 8] = v;
    }
}

// ---------------- kernel: GEMM2: y = h @ w2^T -------------------------------
// grid (H/128, T/128, 4), block 128 (4 warps of 64x64), 2 CTA/SM.
__global__ __launch_bounds__(128, 2)
void k_gemm2(int ebase) {
    int e = blockIdx.z + ebase;
    int cnt = g_cnt[e];
    int m0 = blockIdx.y * 128;
    if (m0 >= cnt) return;
    int n0 = blockIdx.x * 128;

    extern __shared__ char sm[];
    uint32_t sb = smem_u32(sm);

    int tid = threadIdx.x, wid = tid >> 5, lane = tid & 31;
    int wm = (wid & 1) * 64, wn = (wid >> 1) * 64;
    int lr = lane >> 2, lc = lane & 3;
    int lq = lane >> 3, lrr = lane & 7;

    const __half* hbase = g_hh + (size_t)(e * T + m0) * F;
    const __half* w2e   = g_w2h + ((size_t)e * H + n0) * F;

    float acc[4][8][4] = {};

    auto load_tile = [&](int s, int itile) {
        uint32_t abase = sb + TILE0 + s * STAGE_B;
        uint32_t bbase = abase + A_BYTES;
        int k0 = itile * BK;
#pragma unroll
        for (int q = 0; q < 8; q++) {
            int ch = tid + q * 128;
            int r = ch >> 3, c = ch & 7;
            cpa16(abase + r * RSTRIDE + c * 16, hbase + (size_t)r * F + k0 + c * 8);
            cpa16(bbase + r * RSTRIDE + c * 16, w2e + (size_t)r * F + k0 + c * 8);
        }
    };

    load_tile(0, 0); CP_COMMIT();
    load_tile(1, 1); CP_COMMIT();

    const int NIT = F / BK;   // 44
    for (int it = 0; it < NIT; ++it) {
        CP_WAIT1();
        __syncthreads();
        if (it + 2 < NIT) load_tile((it + 2) % NSTAGE, it + 2);
        CP_COMMIT();

        uint32_t abase = sb + TILE0 + (it % NSTAGE) * STAGE_B;
        uint32_t bbase = abase + A_BYTES;
#pragma unroll
        for (int kk = 0; kk < BK; kk += 16) {
            unsigned a[4][4];
#pragma unroll
            for (int i = 0; i < 4; i++) {
                uint32_t ad = abase + (wm + i * 16 + (lane & 15)) * RSTRIDE
                            + kk * 2 + ((lane >> 4) << 4);
                ldsm4(a[i], ad);
            }
            uint32_t koff = (uint32_t)((kk + (lq & 1) * 8) * 2);
            unsigned bcur[4], bnxt[4];
            ldsm4(bcur, bbase + (wn + (lq >> 1) * 8 + lrr) * RSTRIDE + koff);
#pragma unroll
            for (int jp = 0; jp < 4; jp++) {
                if (jp < 3)
                    ldsm4(bnxt, bbase + (wn + (jp + 1) * 16 + (lq >> 1) * 8 + lrr)
                                 * RSTRIDE + koff);
#pragma unroll
                for (int jj = 0; jj < 2; jj++) {
                    int j = jp * 2 + jj;
#pragma unroll
                    for (int i = 0; i < 4; i++)
                        mma_f16(acc[i][j], a[i], bcur[jj * 2], bcur[jj * 2 + 1]);
                }
#pragma unroll
                for (int q = 0; q < 4; q++) bcur[q] = bnxt[q];
            }
        }
    }

    // epilogue: plain stores of unweighted y
#pragma unroll
    for (int i = 0; i < 4; i++) {
#pragma unroll
        for (int p = 0; p < 2; p++) {
            int rr = wm + i * 16 + p * 8 + lr;
            size_t row = (size_t)(e * T + m0 + rr) * H + n0;
#pragma unroll
            for (int j = 0; j < 8; j++) {
                float2 st;
                st.x = acc[i][j][p * 2 + 0];
                st.y = acc[i][j][p * 2 + 1];
                *(float2*)&g_y[row + wn + j * 8 + 2 * lc] = st;
            }
        }
    }
}

// ---------------- kernel: combine (out = w0*y[s0] + w1*y[s1]; re-zero cnt) --
__global__ void k_combine(float* __restrict__ out) {
    int idx = blockIdx.x * blockDim.x + threadIdx.x;   // one float4
    if (blockIdx.x == 0 && threadIdx.x < E) g_cnt[threadIdx.x] = 0;
    if (idx >= T * H / 4) return;
    int t = idx / (H / 4);
    int c = idx % (H / 4);
    int s0 = g_inv[2 * t], s1 = g_inv[2 * t + 1];
    float w0 = g_wt[s0], w1 = g_wt[s1];
    float4 a = *(const float4*)&g_y[(size_t)s0 * H + c * 4];
    float4 b = *(const float4*)&g_y[(size_t)s1 * H + c * 4];
    float4 o;
    o.x = w0 * a.x + w1 * b.x;
    o.y = w0 * a.y + w1 * b.y;
    o.z = w0 * a.z + w1 * b.z;
    o.w = w0 * a.w + w1 * b.w;
    ((float4*)out)[idx] = o;
}

// ---------------- stream/event pool (static init; no device allocations) ----
struct StreamPool {
    cudaStream_t s1, s2, sA, sB;
    cudaEvent_t  e_root, e_p13a, e_p13b, e_init, e_p2, e_router, e_dA, e_dB;
    StreamPool() {
        cudaStreamCreateWithFlags(&s1, cudaStreamNonBlocking);
        cudaStreamCreateWithFlags(&s2, cudaStreamNonBlocking);
        cudaStreamCreateWithFlags(&sA, cudaStreamNonBlocking);
        cudaStreamCreateWithFlags(&sB, cudaStreamNonBlocking);
        cudaEventCreateWithFlags(&e_root,   cudaEventDisableTiming);
        cudaEventCreateWithFlags(&e_p13a,   cudaEventDisableTiming);
        cudaEventCreateWithFlags(&e_p13b,   cudaEventDisableTiming);
        cudaEventCreateWithFlags(&e_init,   cudaEventDisableTiming);
        cudaEventCreateWithFlags(&e_p2,     cudaEventDisableTiming);
        cudaEventCreateWithFlags(&e_router, cudaEventDisableTiming);
        cudaEventCreateWithFlags(&e_dA,     cudaEventDisableTiming);
        cudaEventCreateWithFlags(&e_dB,     cudaEventDisableTiming);
    }
};
static StreamPool g_sp;

// ---------------- launch ----------------------------------------------------
extern "C" void kernel_launch(void* const* d_in, const int* in_sizes, int n_in,
                              void* d_out, int out_size) {
    const float* x  = (const float*)d_in[0];   // [T, H]
    const float* gw = (const float*)d_in[1];   // [E, H]
    const float* w1 = (const float*)d_in[2];   // [E, F, H]
    const float* w3 = (const float*)d_in[3];   // [E, F, H]
    const float* w2 = (const float*)d_in[4];   // [E, H, F]
    float* out = (float*)d_out;                // [T, H]

    cudaFuncSetAttribute(k_gemm1, cudaFuncAttributeMaxDynamicSharedMemorySize, SMEM_SZ);
    cudaFuncSetAttribute(k_gemm2, cudaFuncAttributeMaxDynamicSharedMemorySize, SMEM_SZ);

    // fork side streams off the (captured) default stream
    cudaEventRecord(g_sp.e_root, 0);
    cudaStreamWaitEvent(g_sp.s1, g_sp.e_root, 0);
    cudaStreamWaitEvent(g_sp.s2, g_sp.e_root, 0);
    cudaStreamWaitEvent(g_sp.sA, g_sp.e_root, 0);
    cudaStreamWaitEvent(g_sp.sB, g_sp.e_root, 0);

    // s1: w1/w3 conversion by expert halves (each gates one gemm1 half)
    k_prep13<<<2048, 256, 0, g_sp.s1>>>(w1, w3, 0, E / 2);
    cudaEventRecord(g_sp.e_p13a, g_sp.s1);
    k_prep13<<<2048, 256, 0, g_sp.s1>>>(w1, w3, E / 2, E);
    cudaEventRecord(g_sp.e_p13b, g_sp.s1);

    // s2: x conversion (gates gemm1), then w2 conversion (gates gemm2 only)
    k_init<<<256, 256, 0, g_sp.s2>>>(x);
    cudaEventRecord(g_sp.e_init, g_sp.s2);
    k_prep2<<<2048, 256, 0, g_sp.s2>>>(w2);
    cudaEventRecord(g_sp.e_p2, g_sp.s2);

    // default: routing (counters pre-zeroed by previous combine / static init)
    k_router<<<T / 8, 256>>>(x, gw);
    cudaEventRecord(g_sp.e_router, 0);

    dim3 g1(F / 64, T / 128, E / 2);
    dim3 g2(H / 128, T / 128, E / 2);

    // pipeline A: experts 0..3
    cudaStreamWaitEvent(g_sp.sA, g_sp.e_p13a, 0);
    cudaStreamWaitEvent(g_sp.sA, g_sp.e_init, 0);
    cudaStreamWaitEvent(g_sp.sA, g_sp.e_router, 0);
    k_gemm1<<<g1, 128, SMEM_SZ, g_sp.sA>>>(0);
    cudaStreamWaitEvent(g_sp.sA, g_sp.e_p2, 0);
    k_gemm2<<<g2, 128, SMEM_SZ, g_sp.sA>>>(0);
    cudaEventRecord(g_sp.e_dA, g_sp.sA);

    // pipeline B: experts 4..7
    cudaStreamWaitEvent(g_sp.sB, g_sp.e_p13b, 0);
    cudaStreamWaitEvent(g_sp.sB, g_sp.e_init, 0);
    cudaStreamWaitEvent(g_sp.sB, g_sp.e_router, 0);
    k_gemm1<<<g1, 128, SMEM_SZ, g_sp.sB>>>(E / 2);
    cudaStreamWaitEvent(g_sp.sB, g_sp.e_p2, 0);
    k_gemm2<<<g2, 128, SMEM_SZ, g_sp.sB>>>(E / 2);
    cudaEventRecord(g_sp.e_dB, g_sp.sB);

    // join + combine on default stream
    cudaStreamWaitEvent(0, g_sp.e_dA, 0);
    cudaStreamWaitEvent(0, g_sp.e_dB, 0);
    k_combine<<<(T * H / 4 + 255) / 256, 256>>>(out);
}

// round 16
// speedup vs baseline: 1.1032x; 1.1032x over previous
#include <cuda_runtime.h>
#include <cuda_fp16.h>
#include <math.h>
#include <stdint.h>

#define T 2048
#define H 1024
#define F 2816
#define E 8
#define BK 64          // k (f16 elems) per pipeline stage
#define RSTRIDE 144    // padded row stride in bytes (72 halves)
#define NSTAGE 3

// ---------------- scratch (__device__ globals: allocation-free rule) --------
__device__ int    g_cnt[E];                     // zero-init; re-zeroed by combine
__device__ int    g_tok[E * T];
__device__ float  g_wt [E * T];
__device__ int    g_inv[2 * T];                 // token -> slot (e*T+p)
__device__ __half g_xh [(size_t)T * H];         // fp16 x
__device__ __half g_hh [(size_t)E * T * F];     // fp16 hidden
__device__ __half g_w13h[(size_t)E * 2 * F * H]; // interleaved w1/w3 fp16
__device__ __half g_w2h[(size_t)E * H * F];
__device__ float  g_y  [(size_t)E * T * H];     // unweighted expert outputs

// ---------------- helpers ---------------------------------------------------
__device__ __forceinline__ unsigned h2u(__half2 h) {
    union { __half2 h; unsigned u; } c; c.h = h; return c.u;
}
__device__ __forceinline__ unsigned long long pk4(float4 v) {
    return (unsigned long long)h2u(__floats2half2_rn(v.x, v.y))
         | ((unsigned long long)h2u(__floats2half2_rn(v.z, v.w)) << 32);
}
__device__ __forceinline__ void mma_f16(float d[4], const unsigned a[4],
                                        const unsigned b[2]) {
    asm volatile(
        "mma.sync.aligned.m16n8k16.row.col.f32.f16.f16.f32 "
        "{%0,%1,%2,%3}, {%4,%5,%6,%7}, {%8,%9}, {%0,%1,%2,%3};\n"
        : "+f"(d[0]), "+f"(d[1]), "+f"(d[2]), "+f"(d[3])
        : "r"(a[0]), "r"(a[1]), "r"(a[2]), "r"(a[3]),
          "r"(b[0]), "r"(b[1]));
}
__device__ __forceinline__ void ldsm4(unsigned r[4], uint32_t addr) {
    asm volatile("ldmatrix.sync.aligned.m8n8.x4.shared.b16 {%0,%1,%2,%3}, [%4];"
                 : "=r"(r[0]), "=r"(r[1]), "=r"(r[2]), "=r"(r[3]) : "r"(addr));
}
__device__ __forceinline__ void cpa16(uint32_t dst, const void* src) {
    asm volatile("cp.async.cg.shared.global [%0], [%1], 16;" :: "r"(dst), "l"(src));
}
#define CP_COMMIT() asm volatile("cp.async.commit_group;")
#define CP_WAIT1()  asm volatile("cp.async.wait_group 1;")
__device__ __forceinline__ uint32_t smem_u32(const void* p) {
    return (uint32_t)__cvta_generic_to_shared(p);
}

#define TILE0   1024
#define A_BYTES (128 * RSTRIDE)                  // 18432
#define STAGE_B (2 * A_BYTES)                    // 36864 (A + B)
#define SMEM_SZ (TILE0 + NSTAGE * STAGE_B)       // 111616 -> 2 CTAs/SM

// ---------------- kernel: prep13 (w1,w3 of experts [e0,e1) -> interleaved) --
// dst row (e, 2f) = w1[e][f], (e, 2f+1) = w3[e][f]; dst chunk = 2*rg*256 + c.
__global__ void k_prep13(const float* __restrict__ w1,
                         const float* __restrict__ w3, int e0, int e1) {
    const size_t base = (size_t)e0 * F * (H / 4);
    const size_t n4 = (size_t)(e1 - e0) * F * (H / 4);
    const size_t half = n4 >> 1;
    size_t stride = (size_t)gridDim.x * blockDim.x;
    for (size_t k = blockIdx.x * (size_t)blockDim.x + threadIdx.x; k < half;
         k += stride) {
        size_t i0 = base + k, i1 = base + k + half;
        float4 a0 = __ldcs((const float4*)w1 + i0);
        float4 a1 = __ldcs((const float4*)w1 + i1);
        float4 b0 = __ldcs((const float4*)w3 + i0);
        float4 b1 = __ldcs((const float4*)w3 + i1);
        size_t d0 = ((i0 >> 8) << 9) + (i0 & 255);   // (2*row)*256 + col
        size_t d1 = ((i1 >> 8) << 9) + (i1 & 255);
        __stcs((unsigned long long*)((uint2*)g_w13h + d0),       pk4(a0));
        __stcs((unsigned long long*)((uint2*)g_w13h + d0 + 256), pk4(b0));
        __stcs((unsigned long long*)((uint2*)g_w13h + d1),       pk4(a1));
        __stcs((unsigned long long*)((uint2*)g_w13h + d1 + 256), pk4(b1));
    }
}

// ---------------- kernel: prep2 (w2 -> fp16; streaming, MLP-batched) --------
__global__ void k_prep2(const float* __restrict__ w2) {
    const size_t n4 = (size_t)E * F * H / 4;
    const size_t half = n4 >> 1;
    size_t stride = (size_t)gridDim.x * blockDim.x;
    for (size_t k = blockIdx.x * (size_t)blockDim.x + threadIdx.x; k < half;
         k += stride) {
        size_t i0 = k, i1 = k + half;
        float4 c0 = __ldcs((const float4*)w2 + i0);
        float4 c1 = __ldcs((const float4*)w2 + i1);
        __stcs((unsigned long long*)((uint2*)g_w2h + i0), pk4(c0));
        __stcs((unsigned long long*)((uint2*)g_w2h + i1), pk4(c1));
    }
}

// ---------------- kernel: init (x -> fp16) ----------------------------------
__global__ void k_init(const float* __restrict__ x) {
    const int n4 = T * H / 4;
    for (int i = blockIdx.x * blockDim.x + threadIdx.x; i < n4;
         i += gridDim.x * blockDim.x) {
        float4 a = ((const float4*)x)[i];
        uint2 p; p.x = h2u(__floats2half2_rn(a.x, a.y));
        p.y = h2u(__floats2half2_rn(a.z, a.w));
        ((uint2*)g_xh)[i] = p;
    }
}

// ---------------- kernel: router (vectorized; cnt pre-zeroed by combine) ----
__global__ void k_router(const float* __restrict__ x, const float* __restrict__ gw) {
    int warp = (blockIdx.x * blockDim.x + threadIdx.x) >> 5;
    int lane = threadIdx.x & 31;
    if (warp >= T) return;
    const float4* xr = (const float4*)(x + (size_t)warp * H);
    float4 xv[8];
#pragma unroll
    for (int q = 0; q < 8; q++) xv[q] = xr[lane + q * 32];
    float logit[E];
#pragma unroll
    for (int e = 0; e < E; e++) {
        const float4* g4 = (const float4*)(gw + (size_t)e * H);
        float p = 0.0f;
#pragma unroll
        for (int q = 0; q < 8; q++) {
            float4 gv = g4[lane + q * 32];
            p += xv[q].x * gv.x + xv[q].y * gv.y + xv[q].z * gv.z + xv[q].w * gv.w;
        }
#pragma unroll
        for (int o = 16; o; o >>= 1) p += __shfl_xor_sync(0xffffffffu, p, o);
        logit[e] = p;
    }
    if (lane == 0) {
        int i0 = 0; float v0 = logit[0];
#pragma unroll
        for (int e = 1; e < E; e++)
            if (logit[e] > v0) { v0 = logit[e]; i0 = e; }
        int i1 = -1; float v1 = -3.0e38f;
#pragma unroll
        for (int e = 0; e < E; e++)
            if (e != i0 && logit[e] > v1) { v1 = logit[e]; i1 = e; }
        float w0 = 1.0f / (1.0f + expf(v1 - v0));
        float w1 = 1.0f - w0;
        int p0 = atomicAdd(&g_cnt[i0], 1);
        g_tok[i0 * T + p0] = warp; g_wt[i0 * T + p0] = w0;
        g_inv[2 * warp + 0] = i0 * T + p0;
        int p1 = atomicAdd(&g_cnt[i1], 1);
        g_tok[i1 * T + p1] = warp; g_wt[i1 * T + p1] = w1;
        g_inv[2 * warp + 1] = i1 * T + p1;
    }
}

// ---------------- kernel: GEMM1 (fused interleaved w13) -> g_hh -------------
// grid (F/64, T/128, 4) for experts [ebase, ebase+4), block 256, 2 CTA/SM.
// 3-stage cp.async ring, wait1. Warp tile 64x32i.
__global__ __launch_bounds__(256, 2)
void k_gemm1(int ebase) {
    int e = blockIdx.z + ebase;
    int cnt = g_cnt[e];
    int m0 = blockIdx.y * 128;
    if (m0 >= cnt) return;
    int n0f = blockIdx.x * 64;                   // FFN column base

    extern __shared__ char sm[];
    int* toks = (int*)sm;
    uint32_t sb = smem_u32(sm);

    int tid = threadIdx.x, wid = tid >> 5, lane = tid & 31;
    int wm = (wid & 1) * 64, wn = (wid >> 1) * 32;
    int lr = lane >> 2, lc = lane & 3;
    int lq = lane >> 3, lrr = lane & 7;

    if (tid < 128) toks[tid] = g_tok[e * T + min(m0 + tid, cnt - 1)];
    __syncthreads();

    // interleaved weight rows: tile row r -> global row e*2F + 2*n0f + r
    const __half* w13e = g_w13h + ((size_t)e * 2 * F + 2 * n0f) * H;

    float acc[4][4][4] = {};

    auto load_tile = [&](int s, int itile) {
        uint32_t abase = sb + TILE0 + s * STAGE_B;
        uint32_t bbase = abase + A_BYTES;
        int k0 = itile * BK;
#pragma unroll
        for (int q = 0; q < 4; q++) {            // A: 128 rows x 8 chunks
            int ch = tid + q * 256;
            int r = ch >> 3, c = ch & 7;
            cpa16(abase + r * RSTRIDE + c * 16,
                  g_xh + (size_t)toks[r] * H + k0 + c * 8);
        }
#pragma unroll
        for (int q = 0; q < 4; q++) {            // B: 128 interleaved rows x 8
            int ch = tid + q * 256;
            int r = ch >> 3, c = ch & 7;
            cpa16(bbase + r * RSTRIDE + c * 16,
                  w13e + (size_t)r * H + k0 + c * 8);
        }
    };

    load_tile(0, 0); CP_COMMIT();
    load_tile(1, 1); CP_COMMIT();

    const int NIT = H / BK;   // 16
    for (int it = 0; it < NIT; ++it) {
        CP_WAIT1();                      // tile it resident; it+1 may be in flight
        __syncthreads();                 // stage (it-1)%3 consumed by all warps
        if (it + 2 < NIT) load_tile((it + 2) % NSTAGE, it + 2);
        CP_COMMIT();

        uint32_t abase = sb + TILE0 + (it % NSTAGE) * STAGE_B;
        uint32_t bbase = abase + A_BYTES;
#pragma unroll
        for (int kk = 0; kk < BK; kk += 16) {
            unsigned a[4][4];
#pragma unroll
            for (int i = 0; i < 4; i++) {
                uint32_t ad = abase + (wm + i * 16 + (lane & 15)) * RSTRIDE
                            + kk * 2 + ((lane >> 4) << 4);
                ldsm4(a[i], ad);
            }
            unsigned bf[2][4];
#pragma unroll
            for (int jp = 0; jp < 2; jp++) {
                int nrow = wn + jp * 16 + (lq >> 1) * 8 + lrr;
                uint32_t koff = (uint32_t)((kk + (lq & 1) * 8) * 2);
                ldsm4(bf[jp], bbase + nrow * RSTRIDE + koff);
            }
#pragma unroll
            for (int jp = 0; jp < 2; jp++) {
#pragma unroll
                for (int jj = 0; jj < 2; jj++) {
                    int j = jp * 2 + jj;
                    unsigned b[2] = { bf[jp][jj * 2], bf[jp][jj * 2 + 1] };
#pragma unroll
                    for (int i = 0; i < 4; i++) mma_f16(acc[i][j], a[i], b);
                }
            }
        }
    }

    // epilogue: h = silu(g)*u (register-local), stage fp16 via smem
    __syncthreads();
    __half* hst = (__half*)(sm + TILE0);         // [128][72] halves
#pragma unroll
    for (int i = 0; i < 4; i++) {
#pragma unroll
        for (int p = 0; p < 2; p++) {
            int row = wm + i * 16 + p * 8 + lr;
#pragma unroll
            for (int j = 0; j < 4; j++) {
                float g = acc[i][j][p * 2 + 0];
                float u = acc[i][j][p * 2 + 1];
                float h = g / (1.0f + __expf(-g)) * u;
                int nf = (wn >> 1) + j * 4 + lc;
                hst[row * 72 + nf] = __float2half_rn(h);
            }
        }
    }
    __syncthreads();
#pragma unroll
    for (int q = 0; q < 4; q++) {                // 128 rows x 8 chunks of 8 halves
        int ch = tid + q * 256;
        int r = ch >> 3, c = ch & 7;
        float4 v = *(const float4*)(hst + r * 72 + c * 8);
        *(float4*)&g_hh[(size_t)(e * T + m0 + r) * F + n0f + c * 8] = v;
    }
}

// ---------------- kernel: GEMM2: y = h @ w2^T -------------------------------
// grid (H/128, T/128, 4) for experts [ebase, ebase+4), block 256.
__global__ __launch_bounds__(256, 2)
void k_gemm2(int ebase) {
    int e = blockIdx.z + ebase;
    int cnt = g_cnt[e];
    int m0 = blockIdx.y * 128;
    if (m0 >= cnt) return;
    int n0 = blockIdx.x * 128;

    extern __shared__ char sm[];
    uint32_t sb = smem_u32(sm);

    int tid = threadIdx.x, wid = tid >> 5, lane = tid & 31;
    int wm = (wid & 1) * 64, wn = (wid >> 1) * 32;
    int lr = lane >> 2, lc = lane & 3;
    int lq = lane >> 3, lrr = lane & 7;

    const __half* hbase = g_hh + (size_t)(e * T + m0) * F;
    const __half* w2e   = g_w2h + ((size_t)e * H + n0) * F;

    float acc[4][4][4] = {};

    auto load_tile = [&](int s, int itile) {
        uint32_t abase = sb + TILE0 + s * STAGE_B;
        uint32_t bbase = abase + A_BYTES;
        int k0 = itile * BK;
#pragma unroll
        for (int q = 0; q < 4; q++) {
            int ch = tid + q * 256;
            int r = ch >> 3, c = ch & 7;
            cpa16(abase + r * RSTRIDE + c * 16, hbase + (size_t)r * F + k0 + c * 8);
            cpa16(bbase + r * RSTRIDE + c * 16, w2e + (size_t)r * F + k0 + c * 8);
        }
    };

    load_tile(0, 0); CP_COMMIT();
    load_tile(1, 1); CP_COMMIT();

    const int NIT = F / BK;   // 44
    for (int it = 0; it < NIT; ++it) {
        CP_WAIT1();
        __syncthreads();
        if (it + 2 < NIT) load_tile((it + 2) % NSTAGE, it + 2);
        CP_COMMIT();

        uint32_t abase = sb + TILE0 + (it % NSTAGE) * STAGE_B;
        uint32_t bbase = abase + A_BYTES;
#pragma unroll
        for (int kk = 0; kk < BK; kk += 16) {
            unsigned a[4][4];
#pragma unroll
            for (int i = 0; i < 4; i++) {
                uint32_t ad = abase + (wm + i * 16 + (lane & 15)) * RSTRIDE
                            + kk * 2 + ((lane >> 4) << 4);
                ldsm4(a[i], ad);
            }
            unsigned bf[2][4];
#pragma unroll
            for (int jp = 0; jp < 2; jp++) {
                int nrow = wn + jp * 16 + (lq >> 1) * 8 + lrr;
                uint32_t koff = (uint32_t)((kk + (lq & 1) * 8) * 2);
                ldsm4(bf[jp], bbase + nrow * RSTRIDE + koff);
            }
#pragma unroll
            for (int jp = 0; jp < 2; jp++) {
#pragma unroll
                for (int jj = 0; jj < 2; jj++) {
                    int j = jp * 2 + jj;
                    unsigned b[2] = { bf[jp][jj * 2], bf[jp][jj * 2 + 1] };
#pragma unroll
                    for (int i = 0; i < 4; i++) mma_f16(acc[i][j], a[i], b);
                }
            }
        }
    }

    // epilogue: plain stores of unweighted y
#pragma unroll
    for (int i = 0; i < 4; i++) {
#pragma unroll
        for (int p = 0; p < 2; p++) {
            int rr = wm + i * 16 + p * 8 + lr;
            size_t row = (size_t)(e * T + m0 + rr) * H + n0;
#pragma unroll
            for (int j = 0; j < 4; j++) {
                float2 st;
                st.x = acc[i][j][p * 2 + 0];
                st.y = acc[i][j][p * 2 + 1];
                *(float2*)&g_y[row + wn + j * 8 + 2 * lc] = st;
            }
        }
    }
}

// ---------------- kernel: combine (out = w0*y[s0] + w1*y[s1]; re-zero cnt) --
__global__ void k_combine(float* __restrict__ out) {
    int idx = blockIdx.x * blockDim.x + threadIdx.x;   // one float4
    if (blockIdx.x == 0 && threadIdx.x < E) g_cnt[threadIdx.x] = 0;
    if (idx >= T * H / 4) return;
    int t = idx / (H / 4);
    int c = idx % (H / 4);
    int s0 = g_inv[2 * t], s1 = g_inv[2 * t + 1];
    float w0 = g_wt[s0], w1 = g_wt[s1];
    float4 a = *(const float4*)&g_y[(size_t)s0 * H + c * 4];
    float4 b = *(const float4*)&g_y[(size_t)s1 * H + c * 4];
    float4 o;
    o.x = w0 * a.x + w1 * b.x;
    o.y = w0 * a.y + w1 * b.y;
    o.z = w0 * a.z + w1 * b.z;
    o.w = w0 * a.w + w1 * b.w;
    ((float4*)out)[idx] = o;
}

// ---------------- stream/event pool (static init; no device allocations) ----
struct StreamPool {
    cudaStream_t s1, s2, sA, sB;
    cudaEvent_t  e_root, e_p13a, e_p13b, e_init, e_p2, e_router, e_dA, e_dB;
    StreamPool() {
        cudaStreamCreateWithFlags(&s1, cudaStreamNonBlocking);
        cudaStreamCreateWithFlags(&s2, cudaStreamNonBlocking);
        cudaStreamCreateWithFlags(&sA, cudaStreamNonBlocking);
        cudaStreamCreateWithFlags(&sB, cudaStreamNonBlocking);
        cudaEventCreateWithFlags(&e_root,   cudaEventDisableTiming);
        cudaEventCreateWithFlags(&e_p13a,   cudaEventDisableTiming);
        cudaEventCreateWithFlags(&e_p13b,   cudaEventDisableTiming);
        cudaEventCreateWithFlags(&e_init,   cudaEventDisableTiming);
        cudaEventCreateWithFlags(&e_p2,     cudaEventDisableTiming);
        cudaEventCreateWithFlags(&e_router, cudaEventDisableTiming);
        cudaEventCreateWithFlags(&e_dA,     cudaEventDisableTiming);
        cudaEventCreateWithFlags(&e_dB,     cudaEventDisableTiming);
    }
};
static StreamPool g_sp;

// ---------------- launch ----------------------------------------------------
extern "C" void kernel_launch(void* const* d_in, const int* in_sizes, int n_in,
                              void* d_out, int out_size) {
    const float* x  = (const float*)d_in[0];   // [T, H]
    const float* gw = (const float*)d_in[1];   // [E, H]
    const float* w1 = (const float*)d_in[2];   // [E, F, H]
    const float* w3 = (const float*)d_in[3];   // [E, F, H]
    const float* w2 = (const float*)d_in[4];   // [E, H, F]
    float* out = (float*)d_out;                // [T, H]

    cudaFuncSetAttribute(k_gemm1, cudaFuncAttributeMaxDynamicSharedMemorySize, SMEM_SZ);
    cudaFuncSetAttribute(k_gemm2, cudaFuncAttributeMaxDynamicSharedMemorySize, SMEM_SZ);

    // fork side streams off the (captured) default stream
    cudaEventRecord(g_sp.e_root, 0);
    cudaStreamWaitEvent(g_sp.s1, g_sp.e_root, 0);
    cudaStreamWaitEvent(g_sp.s2, g_sp.e_root, 0);
    cudaStreamWaitEvent(g_sp.sA, g_sp.e_root, 0);
    cudaStreamWaitEvent(g_sp.sB, g_sp.e_root, 0);

    // s1: w1/w3 conversion by expert halves (each gates one gemm1 half)
    k_prep13<<<2048, 256, 0, g_sp.s1>>>(w1, w3, 0, E / 2);
    cudaEventRecord(g_sp.e_p13a, g_sp.s1);
    k_prep13<<<2048, 256, 0, g_sp.s1>>>(w1, w3, E / 2, E);
    cudaEventRecord(g_sp.e_p13b, g_sp.s1);

    // s2: x conversion (gates gemm1), then w2 conversion (gates gemm2 only)
    k_init<<<256, 256, 0, g_sp.s2>>>(x);
    cudaEventRecord(g_sp.e_init, g_sp.s2);
    k_prep2<<<2048, 256, 0, g_sp.s2>>>(w2);
    cudaEventRecord(g_sp.e_p2, g_sp.s2);

    // default: routing (counters pre-zeroed by previous combine / static init)
    k_router<<<T / 8, 256>>>(x, gw);
    cudaEventRecord(g_sp.e_router, 0);

    dim3 g1(F / 64, T / 128, E / 2);
    dim3 g2(H / 128, T / 128, E / 2);

    // pipeline A: experts 0..3
    cudaStreamWaitEvent(g_sp.sA, g_sp.e_p13a, 0);
    cudaStreamWaitEvent(g_sp.sA, g_sp.e_init, 0);
    cudaStreamWaitEvent(g_sp.sA, g_sp.e_router, 0);
    k_gemm1<<<g1, 256, SMEM_SZ, g_sp.sA>>>(0);
    cudaStreamWaitEvent(g_sp.sA, g_sp.e_p2, 0);
    k_gemm2<<<g2, 256, SMEM_SZ, g_sp.sA>>>(0);
    cudaEventRecord(g_sp.e_dA, g_sp.sA);

    // pipeline B: experts 4..7
    cudaStreamWaitEvent(g_sp.sB, g_sp.e_p13b, 0);
    cudaStreamWaitEvent(g_sp.sB, g_sp.e_init, 0);
    cudaStreamWaitEvent(g_sp.sB, g_sp.e_router, 0);
    k_gemm1<<<g1, 256, SMEM_SZ, g_sp.sB>>>(E / 2);
    cudaStreamWaitEvent(g_sp.sB, g_sp.e_p2, 0);
    k_gemm2<<<g2, 256, SMEM_SZ, g_sp.sB>>>(E / 2);
    cudaEventRecord(g_sp.e_dB, g_sp.sB);

    // join + combine on default stream
    cudaStreamWaitEvent(0, g_sp.e_dA, 0);
    cudaStreamWaitEvent(0, g_sp.e_dB, 0);
    k_combine<<<(T * H / 4 + 255) / 256, 256>>>(out);
}